// round 9
// baseline (speedup 1.0000x reference)
#include <cuda_runtime.h>

// VLAD pooling: x [32,4096,128] f32, centroids [64,128] f32 -> out [32, 8192] f32
//
// R7: warp-local softmax (GEMM1 remapped so each point's 64 clusters live in
//     one warp -> register softmax, 3 syncs/tile instead of 4, no logits
//     smem round-trip); GEMM1 scalar FFMA (reg relief), GEMM2 packed fma2;
//     centroid smem gets its own swizzle for the stride-4-row read pattern.

#define B_      32
#define N_      4096
#define D_      128
#define K_      64
#define ALPHA_  100.0f
#define TILE_   64
#define NTILES_ (B_ * (N_ / TILE_))   // 2048 tiles total
#define NCTA_   296                   // 148 SMs * 2 CTAs
#define BASE_T  (NTILES_ / NCTA_)     // 6
#define EXTRA_T (NTILES_ - NCTA_ * BASE_T)  // 272

// shared memory layout (floats)
#define SM_CS 0                    // centroids [64][128], float4 col swizzled by (r>>2)&7
#define SM_C2 8192                 // c2 [64]
#define SM_XS 8256                 // x tile [64][128], float4 col swizzled by r&7
#define SM_X2 16448                // x2 [64]
#define SM_AS 16512                // softmax weights a [64][72] (stride 72)
#define A_STRIDE 72
#define SMEM_FLOATS (SM_AS + TILE_ * A_STRIDE)   // 21120 floats = 84480 B

__device__ float g_vlad[B_ * K_ * D_];
__device__ float g_asum[B_ * K_];

typedef unsigned long long u64t;

__device__ __forceinline__ void upk2(u64t v, float& lo, float& hi) {
    asm("mov.b64 {%0,%1}, %2;" : "=f"(lo), "=f"(hi) : "l"(v));
}
__device__ __forceinline__ u64t pk2(float lo, float hi) {
    u64t r; asm("mov.b64 %0, {%1,%2};" : "=l"(r) : "f"(lo), "f"(hi)); return r;
}
__device__ __forceinline__ u64t fma2(u64t a, u64t b, u64t c) {
    u64t d; asm("fma.rn.f32x2 %0, %1, %2, %3;" : "=l"(d) : "l"(a), "l"(b), "l"(c)); return d;
}

__global__ void vlad_zero() {
    int i = blockIdx.x * blockDim.x + threadIdx.x;
    if (i < B_ * K_ * D_) g_vlad[i] = 0.f;
    if (i < B_ * K_) g_asum[i] = 0.f;
}

__device__ __forceinline__ float dot4acc(float4 a, float4 b, float acc) {
    return fmaf(a.x, b.x, fmaf(a.y, b.y, fmaf(a.z, b.z, fmaf(a.w, b.w, acc))));
}

__global__ __launch_bounds__(256, 2)
void vlad_main(const float* __restrict__ x, const float* __restrict__ cent) {
    extern __shared__ float sm[];
    float* cs = sm + SM_CS;
    float* c2 = sm + SM_C2;
    float* xs = sm + SM_XS;
    float* x2 = sm + SM_X2;
    float* aw = sm + SM_AS;

    const int tid  = threadIdx.x;
    const int cta  = blockIdx.x;
    const int q    = tid & 3;      // quarter of a row for gmem loads
    const int r    = tid >> 2;     // row (point) for gmem loads, 0..63
    const int warp = tid >> 5;
    const int lane = tid & 31;

    // GEMM1 / softmax mapping: warp owns points 8w..8w+7
    const int pgrp = lane & 1;         // which half of the warp's 8 points
    const int kgrp = lane >> 1;        // cluster group 0..15 (4 clusters)
    const int p0   = warp * 8 + pgrp * 4;   // first of this lane's 4 points
    const int kc0  = kgrp * 4;              // first of this lane's 4 clusters
    const int xsw  = (pgrp * 4) & 7;        // xs swizzle base: (p0+i)&7 = xsw+i (i<4)
    const int csw  = kgrp & 7;              // cs swizzle for rows kc0..kc0+3

    // GEMM2 mapping (unchanged): 16 d-octets x 16 k-quads
    const int tn   = tid & 15;
    const int k0   = (tid >> 4) * 4;

    // chunked contiguous tile range for this CTA
    const int start = cta * BASE_T + (cta < EXTRA_T ? cta : EXTRA_T);
    const int cnt   = BASE_T + (cta < EXTRA_T ? 1 : 0);

    // ---- load centroids into smem (swizzled by (row>>2)&7) + c2 ----
    {
        const float4* c4 = (const float4*)cent;
        const int csz = (r >> 2) & 7;
        float csum = 0.f;
        #pragma unroll
        for (int it = 0; it < 8; ++it) {
            int f4 = q + it * 4;
            float4 v = c4[r * 32 + f4];
            ((float4*)(cs + r * 128))[f4 ^ csz] = v;
            csum = dot4acc(v, v, csum);
        }
        csum += __shfl_xor_sync(0xffffffffu, csum, 1);
        csum += __shfl_xor_sync(0xffffffffu, csum, 2);
        if (q == 0) c2[r] = csum;
    }
    __syncthreads();

    // per-lane centroid norms (constant across tiles)
    float c2v[4];
    #pragma unroll
    for (int j = 0; j < 4; ++j) c2v[j] = c2[kc0 + j];

    // persistent register accumulators
    u64t vl2[4][4];
    #pragma unroll
    for (int j = 0; j < 4; ++j)
        #pragma unroll
        for (int p = 0; p < 4; ++p) vl2[j][p] = 0ull;
    float asumr[4] = {0.f, 0.f, 0.f, 0.f};   // per-lane, clusters kc0..kc0+3
    int cur_b = start >> 6;

    for (int it = 0; it < cnt; ++it) {
        const int tg = start + it;
        const int b  = tg >> 6;
        const int t  = tg & 63;

        if (b != cur_b) {
            // flush register accumulators on batch change
            const int base = cur_b * K_ * D_;
            #pragma unroll
            for (int j = 0; j < 4; ++j)
                #pragma unroll
                for (int p = 0; p < 4; ++p) {
                    float lo, hi; upk2(vl2[j][p], lo, hi);
                    atomicAdd(&g_vlad[base + (k0 + j) * D_ + tn * 8 + 2 * p], lo);
                    atomicAdd(&g_vlad[base + (k0 + j) * D_ + tn * 8 + 2 * p + 1], hi);
                    vl2[j][p] = 0ull;
                }
            #pragma unroll
            for (int j = 0; j < 4; ++j) {
                atomicAdd(&g_asum[cur_b * K_ + kc0 + j], asumr[j]);
                asumr[j] = 0.f;
            }
            cur_b = b;
        }

        __syncthreads();  // previous tile's GEMM2 reads of xs/aw complete

        // ---- load x tile (float4 col swizzled by row&7) + x2 ----
        {
            const int rowg = b * N_ + t * TILE_ + r;
            const float4* x4 = (const float4*)x;
            const int xsz = r & 7;
            float xsum = 0.f;
            #pragma unroll
            for (int i8 = 0; i8 < 8; ++i8) {
                int f4 = q + i8 * 4;
                float4 v = x4[rowg * 32 + f4];
                ((float4*)(xs + r * 128))[f4 ^ xsz] = v;
                xsum = dot4acc(v, v, xsum);
            }
            xsum += __shfl_xor_sync(0xffffffffu, xsum, 1);
            xsum += __shfl_xor_sync(0xffffffffu, xsum, 2);
            if (q == 0) x2[r] = xsum;
        }
        __syncthreads();

        // ---- GEMM1 (scalar FFMA): 4 points {p0..p0+3} x 4 clusters {kc0..kc0+3} ----
        float acc[4][4];
        #pragma unroll
        for (int i = 0; i < 4; ++i)
            #pragma unroll
            for (int j = 0; j < 4; ++j) acc[i][j] = 0.f;

        #pragma unroll 4
        for (int d4 = 0; d4 < 32; ++d4) {
            float4 xv[4], cv[4];
            #pragma unroll
            for (int i = 0; i < 4; ++i)
                xv[i] = ((const float4*)(xs + (p0 + i) * 128))[d4 ^ ((xsw + i) & 7)];
            #pragma unroll
            for (int j = 0; j < 4; ++j)
                cv[j] = ((const float4*)(cs + (kc0 + j) * 128))[d4 ^ csw];
            #pragma unroll
            for (int i = 0; i < 4; ++i)
                #pragma unroll
                for (int j = 0; j < 4; ++j)
                    acc[i][j] = dot4acc(xv[i], cv[j], acc[i][j]);
        }

        // ---- logits + warp-local softmax (clusters of point p0+i live in the
        //      16 lanes sharing bit0; reduce via shfl_xor 2/4/8/16) ----
        #pragma unroll
        for (int i = 0; i < 4; ++i) {
            const float xx = x2[p0 + i];
            float lg[4];
            #pragma unroll
            for (int j = 0; j < 4; ++j) {
                float d2 = fmaxf(xx + c2v[j] - 2.f * acc[i][j], 0.f);
                lg[j] = -ALPHA_ * sqrtf(d2);
            }
            float m = fmaxf(fmaxf(lg[0], lg[1]), fmaxf(lg[2], lg[3]));
            #pragma unroll
            for (int o = 2; o <= 16; o <<= 1)
                m = fmaxf(m, __shfl_xor_sync(0xffffffffu, m, o));
            float e[4];
            float s = 0.f;
            #pragma unroll
            for (int j = 0; j < 4; ++j) { e[j] = __expf(lg[j] - m); s += e[j]; }
            #pragma unroll
            for (int o = 2; o <= 16; o <<= 1)
                s += __shfl_xor_sync(0xffffffffu, s, o);
            const float inv = 1.0f / s;
            float4 a4;
            a4.x = e[0] * inv; a4.y = e[1] * inv; a4.z = e[2] * inv; a4.w = e[3] * inv;
            asumr[0] += a4.x; asumr[1] += a4.y; asumr[2] += a4.z; asumr[3] += a4.w;
            *(float4*)(aw + (p0 + i) * A_STRIDE + kc0) = a4;
        }
        __syncthreads();

        // ---- GEMM2 (fma2): vl2[k0..k0+3][4 d-pairs @ d0=tn*8] += a[n][k] * x[n][d] ----
        #pragma unroll 4
        for (int n = 0; n < TILE_; ++n) {
            float4 av = *(const float4*)(aw + n * A_STRIDE + k0);
            const ulonglong2* xrow = (const ulonglong2*)(xs + n * 128);
            const int swz = n & 7;
            ulonglong2 xa = xrow[(2 * tn) ^ swz];       // logical d4 = 2*tn
            ulonglong2 xb = xrow[(2 * tn + 1) ^ swz];   // logical d4 = 2*tn+1
            u64t xp[4] = {xa.x, xa.y, xb.x, xb.y};
            u64t w2[4] = {pk2(av.x, av.x), pk2(av.y, av.y),
                          pk2(av.z, av.z), pk2(av.w, av.w)};
            #pragma unroll
            for (int j = 0; j < 4; ++j)
                #pragma unroll
                for (int p = 0; p < 4; ++p)
                    vl2[j][p] = fma2(w2[j], xp[p], vl2[j][p]);
        }
    }

    // ---- final flush of register accumulators ----
    const int base = cur_b * K_ * D_;
    #pragma unroll
    for (int j = 0; j < 4; ++j)
        #pragma unroll
        for (int p = 0; p < 4; ++p) {
            float lo, hi; upk2(vl2[j][p], lo, hi);
            atomicAdd(&g_vlad[base + (k0 + j) * D_ + tn * 8 + 2 * p], lo);
            atomicAdd(&g_vlad[base + (k0 + j) * D_ + tn * 8 + 2 * p + 1], hi);
        }
    #pragma unroll
    for (int j = 0; j < 4; ++j)
        atomicAdd(&g_asum[cur_b * K_ + kc0 + j], asumr[j]);
}

__global__ __launch_bounds__(256)
void vlad_finalize(const float* __restrict__ cent, float* __restrict__ out) {
    const int b = blockIdx.x;
    const int tid = threadIdx.x;
    float v[32];
    float ssq = 0.f;
    #pragma unroll
    for (int m = 0; m < 32; ++m) {
        const int e = m * 256 + tid;
        const int k = e >> 7;
        const int d = e & 127;
        float val = fmaf(-g_asum[b * K_ + k], cent[k * D_ + d], g_vlad[b * K_ * D_ + e]);
        v[m] = val;
        ssq = fmaf(val, val, ssq);
    }
    #pragma unroll
    for (int o = 16; o > 0; o >>= 1)
        ssq += __shfl_xor_sync(0xffffffffu, ssq, o);

    __shared__ float red[8];
    __shared__ float s_inv;
    if ((tid & 31) == 0) red[tid >> 5] = ssq;
    __syncthreads();
    if (tid == 0) {
        float tot = 0.f;
        #pragma unroll
        for (int w = 0; w < 8; ++w) tot += red[w];
        float nrm = fmaxf(sqrtf(tot), 1e-12f);
        s_inv = 1.0f / nrm;
    }
    __syncthreads();
    const float inv = s_inv;
    #pragma unroll
    for (int m = 0; m < 32; ++m)
        out[b * K_ * D_ + m * 256 + tid] = v[m] * inv;
}

extern "C" void kernel_launch(void* const* d_in, const int* in_sizes, int n_in,
                              void* d_out, int out_size) {
    const float* x    = (const float*)d_in[0];   // [32,4096,128] f32
    const float* cent = (const float*)d_in[1];   // [64,128] f32
    float* out = (float*)d_out;                  // [32,8192] f32
    (void)in_sizes; (void)n_in; (void)out_size;

    cudaFuncSetAttribute(vlad_main, cudaFuncAttributeMaxDynamicSharedMemorySize,
                         SMEM_FLOATS * (int)sizeof(float));

    vlad_zero<<<(B_ * K_ * D_ + 255) / 256, 256>>>();
    vlad_main<<<NCTA_, 256, SMEM_FLOATS * sizeof(float)>>>(x, cent);
    vlad_finalize<<<B_, 256>>>(cent, out);
}

// round 14
// speedup vs baseline: 2.5121x; 2.5121x over previous
#include <cuda_runtime.h>
#include <cstdint>

// VLAD pooling via warp-level bf16 MMA (mma.sync m16n8k16, base-target safe).
// x [32,4096,128] f32, centroids [64,128] f32 -> out [32, 8192] f32
//
// Per CTA (256 thr = 8 warps, 1/SM, 148 CTAs, 6-7 tiles of 128 points):
//   GEMM1: D1[n,k] = x.c^T  (bf16 split: hi.hi + hi.lo + lo.hi)
//   softmax in fragments (quad shfl), a -> smem bf16 hi/lo
//   GEMM2: D2[d,k] += xT.a  (ldmatrix.trans on both operands, bf16 split)
// D2 + asum persist in registers across tiles; flushed via atomicAdd.
//
// R14: fix x loader (full 128 dims: i8<16), B operands via ldmatrix.x4.

#define B_     32
#define N_     4096
#define D_     128
#define K_     64
#define ALPHA_ 100.0f
#define TILEP  128
#define NT_    1024          // 32 batches * 32 tiles
#define NCTA_  148
#define BASE_T 6
#define EXTRA_T 136          // NT_ - NCTA_*BASE_T

#define XROW 272             // 128 bf16 = 256B, padded +16 (bank rotation 4/row)
#define AROW 144             // 64 bf16 = 128B, padded +16

#define SM_XHI 0
#define SM_XLO 34816         // 128*272
#define SM_CHI 69632
#define SM_CLO 87040         // + 64*272
#define SM_AHI 104448
#define SM_ALO 122880        // + 128*144
#define SM_X2  141312        // 128 f32
#define SM_C2  141824        // 64 f32
#define SMEM_BYTES 142336

__device__ float g_vlad[B_ * K_ * D_];
__device__ float g_asum[B_ * K_];

__global__ void vlad_zero() {
    int i = blockIdx.x * blockDim.x + threadIdx.x;
    if (i < B_ * K_ * D_) g_vlad[i] = 0.f;
    if (i < B_ * K_) g_asum[i] = 0.f;
}

// ---------------- helpers ---------------------------------------------------
__device__ __forceinline__ uint32_t smem_u32(const void* p) {
    uint32_t a;
    asm("{ .reg .u64 t; cvta.to.shared.u64 t, %1; cvt.u32.u64 %0, t; }" : "=r"(a) : "l"(p));
    return a;
}
// pack two f32 -> bf16x2 (lo = low 16 bits = lower address)
__device__ __forceinline__ uint32_t pkbf(float lo, float hi) {
    uint32_t r;
    asm("cvt.rn.bf16x2.f32 %0, %1, %2;" : "=r"(r) : "f"(hi), "f"(lo));
    return r;
}
// split two f32 into bf16 hi-word + bf16 lo-word (residual)
__device__ __forceinline__ void split2(float v0, float v1, uint32_t& hw, uint32_t& lw) {
    hw = pkbf(v0, v1);
    float h0 = __uint_as_float(hw << 16);
    float h1 = __uint_as_float(hw & 0xffff0000u);
    lw = pkbf(v0 - h0, v1 - h1);
}
__device__ __forceinline__ void ldm_x4(uint32_t addr, uint32_t* r) {
    asm volatile("ldmatrix.sync.aligned.m8n8.x4.shared.b16 {%0,%1,%2,%3}, [%4];"
        : "=r"(r[0]), "=r"(r[1]), "=r"(r[2]), "=r"(r[3]) : "r"(addr));
}
__device__ __forceinline__ void ldm_x4t(uint32_t addr, uint32_t* r) {
    asm volatile("ldmatrix.sync.aligned.m8n8.x4.trans.shared.b16 {%0,%1,%2,%3}, [%4];"
        : "=r"(r[0]), "=r"(r[1]), "=r"(r[2]), "=r"(r[3]) : "r"(addr));
}
__device__ __forceinline__ void mma_bf16(float* c, const uint32_t* a, const uint32_t* b) {
    asm volatile("mma.sync.aligned.m16n8k16.row.col.f32.bf16.bf16.f32 "
        "{%0,%1,%2,%3}, {%4,%5,%6,%7}, {%8,%9}, {%0,%1,%2,%3};"
        : "+f"(c[0]), "+f"(c[1]), "+f"(c[2]), "+f"(c[3])
        : "r"(a[0]), "r"(a[1]), "r"(a[2]), "r"(a[3]), "r"(b[0]), "r"(b[1]));
}

// ---------------------------------------------------------------------------
__global__ __launch_bounds__(256, 1)
void vlad_main_mma(const float* __restrict__ x, const float* __restrict__ cent) {
    extern __shared__ char sm[];
    const uint32_t smb = smem_u32(sm);
    float* x2s = (float*)(sm + SM_X2);
    float* c2s = (float*)(sm + SM_C2);

    const int tid  = threadIdx.x;
    const int w    = tid >> 5;
    const int lane = tid & 31;
    const int cta  = blockIdx.x;
    const int r4   = lane >> 2;      // fragment row within 8
    const int q4   = lane & 3;       // fragment col-pair
    const int n0   = w * 16;         // GEMM1: this warp's 16 points
    const int d0   = w * 16;         // GEMM2: this warp's 16 dims

    const int start = cta * BASE_T + (cta < EXTRA_T ? cta : EXTRA_T);
    const int cnt   = BASE_T + (cta < EXTRA_T ? 1 : 0);

    // ---- centroids -> CHI/CLO + c2 ----
    {
        const int q = tid & 3, r = tid >> 2;       // r in [0,64)
        const float4* c4 = (const float4*)cent;
        float csum = 0.f;
        char* rowp_h = sm + SM_CHI + r * XROW;
        #pragma unroll
        for (int it = 0; it < 8; ++it) {
            int f4 = q + it * 4;
            float4 v = c4[r * 32 + f4];
            csum += v.x * v.x + v.y * v.y + v.z * v.z + v.w * v.w;
            uint2 hw, lw;
            split2(v.x, v.y, hw.x, lw.x);
            split2(v.z, v.w, hw.y, lw.y);
            *(uint2*)(rowp_h + f4 * 8) = hw;
            *(uint2*)(rowp_h + (SM_CLO - SM_CHI) + f4 * 8) = lw;
        }
        csum += __shfl_xor_sync(0xffffffffu, csum, 1);
        csum += __shfl_xor_sync(0xffffffffu, csum, 2);
        if (q == 0) c2s[r] = csum;
    }
    __syncthreads();

    // per-lane centroid norms for softmax (constant)
    float c2v[16];
    #pragma unroll
    for (int j = 0; j < 8; ++j) {
        c2v[2 * j]     = c2s[j * 8 + q4 * 2];
        c2v[2 * j + 1] = c2s[j * 8 + q4 * 2 + 1];
    }

    // persistent accumulators
    float acc2[8][4];
    #pragma unroll
    for (int j = 0; j < 8; ++j)
        #pragma unroll
        for (int c = 0; c < 4; ++c) acc2[j][c] = 0.f;
    float asum[16];
    #pragma unroll
    for (int i = 0; i < 16; ++i) asum[i] = 0.f;
    int cur_b = start >> 5;    // 32 tiles per batch

    // ldmatrix base addresses (per lane)
    const uint32_t g1a  = smb + SM_XHI + (uint32_t)((n0 + (lane & 15)) * XROW
                         + (((lane >> 4) & 1) << 4));
    // GEMM1 B x4: t0=(kc+0..7,d+0) t1=(kc+0..7,d+16B) t2=(kc+8..15,d+0) t3=(kc+8..15,+16B)
    const uint32_t g1b4 = smb + SM_CHI + (uint32_t)(((lane & 7) + (((lane >> 4) & 1) << 3)) * XROW
                         + (((lane >> 3) & 1) << 4));
    const uint32_t g2a  = smb + SM_XHI + (uint32_t)(((((lane >> 4) & 1) << 3) + (lane & 7)) * XROW
                         + d0 * 2 + (((lane >> 3) & 1) << 4));
    // GEMM2 B x4t: t0=(n0-7,kc) t1=(n8-15,kc) t2=(n0-7,kc+8) t3=(n8-15,kc+8)
    const uint32_t g2b4 = smb + SM_AHI + (uint32_t)(((lane & 7) + (((lane >> 3) & 1) << 3)) * AROW
                         + (((lane >> 4) & 1) << 4));

    for (int it = 0; it < cnt; ++it) {
        const int tg = start + it;
        const int b  = tg >> 5;
        const int t  = tg & 31;

        if (b != cur_b) {
            // flush register accumulators (regs + atomics only, no smem)
            float* gv = g_vlad + cur_b * K_ * D_;
            const int dd = d0 + r4;
            #pragma unroll
            for (int j = 0; j < 8; ++j) {
                const int kc = j * 8 + q4 * 2;
                atomicAdd(&gv[kc * D_ + dd],           acc2[j][0]);
                atomicAdd(&gv[(kc + 1) * D_ + dd],     acc2[j][1]);
                atomicAdd(&gv[kc * D_ + dd + 8],       acc2[j][2]);
                atomicAdd(&gv[(kc + 1) * D_ + dd + 8], acc2[j][3]);
                acc2[j][0] = acc2[j][1] = acc2[j][2] = acc2[j][3] = 0.f;
            }
            #pragma unroll
            for (int i = 0; i < 16; ++i) {
                float v = asum[i];
                v += __shfl_xor_sync(0xffffffffu, v, 4);
                v += __shfl_xor_sync(0xffffffffu, v, 8);
                v += __shfl_xor_sync(0xffffffffu, v, 16);
                if (lane < 4)
                    atomicAdd(&g_asum[cur_b * K_ + (i >> 1) * 8 + lane * 2 + (i & 1)], v);
                asum[i] = 0.f;
            }
            cur_b = b;
        }

        __syncthreads();   // all warps finished reading previous tile's smem

        // ---- load x tile -> XHI/XLO + x2 (FULL 128 dims: 16 float4/thread) ----
        {
            const int q2 = tid & 1, r2 = tid >> 1;   // r2 in [0,128)
            const int rowg = b * N_ + t * TILEP + r2;
            const float4* xg = (const float4*)x + (size_t)rowg * 32;
            char* rowp = sm + SM_XHI + r2 * XROW;
            float xsum = 0.f;
            #pragma unroll
            for (int i8 = 0; i8 < 16; ++i8) {
                int f4 = q2 + i8 * 2;
                float4 v = xg[f4];
                xsum += v.x * v.x + v.y * v.y + v.z * v.z + v.w * v.w;
                uint2 hw, lw;
                split2(v.x, v.y, hw.x, lw.x);
                split2(v.z, v.w, hw.y, lw.y);
                *(uint2*)(rowp + f4 * 8) = hw;
                *(uint2*)(rowp + (SM_XLO - SM_XHI) + f4 * 8) = lw;
            }
            xsum += __shfl_xor_sync(0xffffffffu, xsum, 1);
            if (q2 == 0) x2s[r2] = xsum;
        }
        __syncthreads();

        // ---- GEMM1: D1[16 n x 64 kc] = x.c^T, bf16 split ----
        float acc1[8][4];
        #pragma unroll
        for (int j = 0; j < 8; ++j)
            #pragma unroll
            for (int c = 0; c < 4; ++c) acc1[j][c] = 0.f;

        #pragma unroll
        for (int ks = 0; ks < 8; ++ks) {
            uint32_t ah[4], al[4];
            ldm_x4(g1a + ks * 32, ah);
            ldm_x4(g1a + (SM_XLO - SM_XHI) + ks * 32, al);
            #pragma unroll
            for (int jj = 0; jj < 4; ++jj) {
                uint32_t bh[4], bl[4];
                uint32_t ba = g1b4 + jj * (16 * XROW) + ks * 32;
                ldm_x4(ba, bh);
                ldm_x4(ba + (SM_CLO - SM_CHI), bl);
                mma_bf16(acc1[2 * jj],     ah, bh);
                mma_bf16(acc1[2 * jj],     ah, bl);
                mma_bf16(acc1[2 * jj],     al, bh);
                mma_bf16(acc1[2 * jj + 1], ah, bh + 2);
                mma_bf16(acc1[2 * jj + 1], ah, bl + 2);
                mma_bf16(acc1[2 * jj + 1], al, bh + 2);
            }
        }

        // ---- softmax in fragments (points pa = n0+r4, pb = pa+8) ----
        {
            const int pa = n0 + r4, pb = pa + 8;
            const float xa = x2s[pa], xb = x2s[pb];
            float lga[16], lgb[16];
            float ma = -1e30f, mb = -1e30f;
            #pragma unroll
            for (int j = 0; j < 8; ++j) {
                #pragma unroll
                for (int c = 0; c < 2; ++c) {
                    float la = -ALPHA_ * sqrtf(fmaxf(xa + c2v[2 * j + c] - 2.f * acc1[j][c], 0.f));
                    float lb = -ALPHA_ * sqrtf(fmaxf(xb + c2v[2 * j + c] - 2.f * acc1[j][2 + c], 0.f));
                    lga[2 * j + c] = la; lgb[2 * j + c] = lb;
                    ma = fmaxf(ma, la);  mb = fmaxf(mb, lb);
                }
            }
            ma = fmaxf(ma, __shfl_xor_sync(0xffffffffu, ma, 1));
            ma = fmaxf(ma, __shfl_xor_sync(0xffffffffu, ma, 2));
            mb = fmaxf(mb, __shfl_xor_sync(0xffffffffu, mb, 1));
            mb = fmaxf(mb, __shfl_xor_sync(0xffffffffu, mb, 2));
            float sa = 0.f, sb = 0.f;
            #pragma unroll
            for (int i = 0; i < 16; ++i) {
                lga[i] = __expf(lga[i] - ma); sa += lga[i];
                lgb[i] = __expf(lgb[i] - mb); sb += lgb[i];
            }
            sa += __shfl_xor_sync(0xffffffffu, sa, 1);
            sa += __shfl_xor_sync(0xffffffffu, sa, 2);
            sb += __shfl_xor_sync(0xffffffffu, sb, 1);
            sb += __shfl_xor_sync(0xffffffffu, sb, 2);
            const float inva = 1.0f / sa, invb = 1.0f / sb;
            char* aw_a = sm + SM_AHI + pa * AROW + q4 * 4;
            char* aw_b = sm + SM_AHI + pb * AROW + q4 * 4;
            #pragma unroll
            for (int j = 0; j < 8; ++j) {
                float a0 = lga[2 * j] * inva,  a1 = lga[2 * j + 1] * inva;
                float b0 = lgb[2 * j] * invb,  b1 = lgb[2 * j + 1] * invb;
                asum[2 * j]     += a0 + b0;
                asum[2 * j + 1] += a1 + b1;
                uint32_t hw, lw;
                split2(a0, a1, hw, lw);
                *(uint32_t*)(aw_a + j * 16) = hw;
                *(uint32_t*)(aw_a + (SM_ALO - SM_AHI) + j * 16) = lw;
                split2(b0, b1, hw, lw);
                *(uint32_t*)(aw_b + j * 16) = hw;
                *(uint32_t*)(aw_b + (SM_ALO - SM_AHI) + j * 16) = lw;
            }
        }
        __syncthreads();   // a-tiles visible to all warps

        // ---- GEMM2: D2[16 d x 64 kc] += xT.a, trans loads, bf16 split ----
        #pragma unroll
        for (int ns = 0; ns < 8; ++ns) {
            uint32_t ah[4], al[4];
            ldm_x4t(g2a + ns * (16 * XROW), ah);
            ldm_x4t(g2a + (SM_XLO - SM_XHI) + ns * (16 * XROW), al);
            #pragma unroll
            for (int jj = 0; jj < 4; ++jj) {
                uint32_t bh[4], bl[4];
                uint32_t ba = g2b4 + ns * (16 * AROW) + jj * 32;
                ldm_x4t(ba, bh);
                ldm_x4t(ba + (SM_ALO - SM_AHI), bl);
                mma_bf16(acc2[2 * jj],     ah, bh);
                mma_bf16(acc2[2 * jj],     ah, bl);
                mma_bf16(acc2[2 * jj],     al, bh);
                mma_bf16(acc2[2 * jj + 1], ah, bh + 2);
                mma_bf16(acc2[2 * jj + 1], ah, bl + 2);
                mma_bf16(acc2[2 * jj + 1], al, bh + 2);
            }
        }
    }

    // ---- final flush ----
    {
        float* gv = g_vlad + cur_b * K_ * D_;
        const int dd = d0 + r4;
        #pragma unroll
        for (int j = 0; j < 8; ++j) {
            const int kc = j * 8 + q4 * 2;
            atomicAdd(&gv[kc * D_ + dd],           acc2[j][0]);
            atomicAdd(&gv[(kc + 1) * D_ + dd],     acc2[j][1]);
            atomicAdd(&gv[kc * D_ + dd + 8],       acc2[j][2]);
            atomicAdd(&gv[(kc + 1) * D_ + dd + 8], acc2[j][3]);
        }
        #pragma unroll
        for (int i = 0; i < 16; ++i) {
            float v = asum[i];
            v += __shfl_xor_sync(0xffffffffu, v, 4);
            v += __shfl_xor_sync(0xffffffffu, v, 8);
            v += __shfl_xor_sync(0xffffffffu, v, 16);
            if (lane < 4)
                atomicAdd(&g_asum[cur_b * K_ + (i >> 1) * 8 + lane * 2 + (i & 1)], v);
        }
    }
}

// ---------------------------------------------------------------------------
__global__ __launch_bounds__(256)
void vlad_finalize(const float* __restrict__ cent, float* __restrict__ out) {
    const int b = blockIdx.x;
    const int tid = threadIdx.x;
    float v[32];
    float ssq = 0.f;
    #pragma unroll
    for (int m = 0; m < 32; ++m) {
        const int e = m * 256 + tid;
        const int k = e >> 7;
        const int d = e & 127;
        float val = fmaf(-g_asum[b * K_ + k], cent[k * D_ + d], g_vlad[b * K_ * D_ + e]);
        v[m] = val;
        ssq = fmaf(val, val, ssq);
    }
    #pragma unroll
    for (int o = 16; o > 0; o >>= 1)
        ssq += __shfl_xor_sync(0xffffffffu, ssq, o);

    __shared__ float red[8];
    __shared__ float s_inv;
    if ((tid & 31) == 0) red[tid >> 5] = ssq;
    __syncthreads();
    if (tid == 0) {
        float tot = 0.f;
        #pragma unroll
        for (int wv = 0; wv < 8; ++wv) tot += red[wv];
        s_inv = 1.0f / fmaxf(sqrtf(tot), 1e-12f);
    }
    __syncthreads();
    const float inv = s_inv;
    #pragma unroll
    for (int m = 0; m < 32; ++m)
        out[b * K_ * D_ + m * 256 + tid] = v[m] * inv;
}

extern "C" void kernel_launch(void* const* d_in, const int* in_sizes, int n_in,
                              void* d_out, int out_size) {
    const float* x    = (const float*)d_in[0];   // [32,4096,128] f32
    const float* cent = (const float*)d_in[1];   // [64,128] f32
    float* out = (float*)d_out;                  // [32,8192] f32
    (void)in_sizes; (void)n_in; (void)out_size;

    cudaFuncSetAttribute(vlad_main_mma, cudaFuncAttributeMaxDynamicSharedMemorySize,
                         SMEM_BYTES);

    vlad_zero<<<(B_ * K_ * D_ + 255) / 256, 256>>>();
    vlad_main_mma<<<NCTA_, 256, SMEM_BYTES>>>(x, cent);
    vlad_finalize<<<B_, 256>>>(cent, out);
}

// round 15
// speedup vs baseline: 2.6871x; 1.0697x over previous
#include <cuda_runtime.h>
#include <cstdint>

// VLAD pooling via warp-level bf16 MMA (mma.sync m16n8k16, base-target safe).
// x [32,4096,128] f32, centroids [64,128] f32 -> out [32, 8192] f32
//
// R15: double-buffered x tiles with register prefetch (DRAM + convert hidden
//      under GEMM1/softmax), rsqrt-based fast sqrt, finalize fused into the
//      main kernel via per-batch last-flusher counters (2 kernels total).

#define B_     32
#define N_     4096
#define D_     128
#define K_     64
#define ALPHA_ 100.0f
#define TILEP  128
#define NT_    1024          // 32 batches * 32 tiles
#define NCTA_  148
#define BASE_T 6
#define EXTRA_T 136          // NT_ - NCTA_*BASE_T  (ctas 0..135 own 7 tiles)

#define XROW 272             // 128 bf16 = 256B, padded +16
#define AROW 144             // 64 bf16 = 128B, padded +16
#define XBUF 34816           // 128*XROW (one hi or lo plane)

#define SM_X0HI 0
#define SM_X0LO 34816
#define SM_X1HI 69632
#define SM_X1LO 104448
#define SM_CHI  139264
#define SM_CLO  156672
#define SM_AHI  174080
#define SM_ALO  192512
#define SM_X2   210944       // 2 x 128 f32 (per x buffer)
#define SM_C2   211968       // 64 f32
#define SMEM_BYTES 212224

__device__ float g_vlad[B_ * K_ * D_];
__device__ float g_asum[B_ * K_];
__device__ int   g_done[B_];

__global__ void vlad_zero() {
    int i = blockIdx.x * blockDim.x + threadIdx.x;
    if (i < B_ * K_ * D_) g_vlad[i] = 0.f;
    if (i < B_ * K_) g_asum[i] = 0.f;
    if (i < B_) g_done[i] = 0;
}

// ---------------- helpers ---------------------------------------------------
__device__ __forceinline__ uint32_t smem_u32(const void* p) {
    uint32_t a;
    asm("{ .reg .u64 t; cvta.to.shared.u64 t, %1; cvt.u32.u64 %0, t; }" : "=r"(a) : "l"(p));
    return a;
}
__device__ __forceinline__ uint32_t pkbf(float lo, float hi) {
    uint32_t r;
    asm("cvt.rn.bf16x2.f32 %0, %1, %2;" : "=r"(r) : "f"(hi), "f"(lo));
    return r;
}
__device__ __forceinline__ void split2(float v0, float v1, uint32_t& hw, uint32_t& lw) {
    hw = pkbf(v0, v1);
    float h0 = __uint_as_float(hw << 16);
    float h1 = __uint_as_float(hw & 0xffff0000u);
    lw = pkbf(v0 - h0, v1 - h1);
}
__device__ __forceinline__ void ldm_x4(uint32_t addr, uint32_t* r) {
    asm volatile("ldmatrix.sync.aligned.m8n8.x4.shared.b16 {%0,%1,%2,%3}, [%4];"
        : "=r"(r[0]), "=r"(r[1]), "=r"(r[2]), "=r"(r[3]) : "r"(addr));
}
__device__ __forceinline__ void ldm_x4t(uint32_t addr, uint32_t* r) {
    asm volatile("ldmatrix.sync.aligned.m8n8.x4.trans.shared.b16 {%0,%1,%2,%3}, [%4];"
        : "=r"(r[0]), "=r"(r[1]), "=r"(r[2]), "=r"(r[3]) : "r"(addr));
}
__device__ __forceinline__ void mma_bf16(float* c, const uint32_t* a, const uint32_t* b) {
    asm volatile("mma.sync.aligned.m16n8k16.row.col.f32.bf16.bf16.f32 "
        "{%0,%1,%2,%3}, {%4,%5,%6,%7}, {%8,%9}, {%0,%1,%2,%3};"
        : "+f"(c[0]), "+f"(c[1]), "+f"(c[2]), "+f"(c[3])
        : "r"(a[0]), "r"(a[1]), "r"(a[2]), "r"(a[3]), "r"(b[0]), "r"(b[1]));
}
// global tile index -> owning CTA (chunk math: ctas 0..135 own 7, rest own 6)
__device__ __forceinline__ int ctaOf(int t) {
    return t < 7 * EXTRA_T ? t / 7 : (t - EXTRA_T) / 6;
}

// ---------------------------------------------------------------------------
__global__ __launch_bounds__(256, 1)
void vlad_main_mma(const float* __restrict__ x, const float* __restrict__ cent,
                   float* __restrict__ out) {
    extern __shared__ char sm[];
    const uint32_t smb = smem_u32(sm);
    float* x2s = (float*)(sm + SM_X2);     // [2][128]
    float* c2s = (float*)(sm + SM_C2);
    __shared__ int   s_isLast;
    __shared__ float s_red[8];
    __shared__ float s_inv;

    const int tid  = threadIdx.x;
    const int w    = tid >> 5;
    const int lane = tid & 31;
    const int cta  = blockIdx.x;
    const int r4   = lane >> 2;
    const int q4   = lane & 3;
    const int n0   = w * 16;
    const int d0   = w * 16;
    const int q2   = tid & 1;        // x loader: 2 threads per row
    const int r2   = tid >> 1;       // row 0..127

    const int start = cta * BASE_T + (cta < EXTRA_T ? cta : EXTRA_T);
    const int cnt   = BASE_T + (cta < EXTRA_T ? 1 : 0);

    // ---- centroids -> CHI/CLO + c2 ----
    {
        const int q = tid & 3, r = tid >> 2;       // r in [0,64)
        const float4* c4 = (const float4*)cent;
        float csum = 0.f;
        char* rowp_h = sm + SM_CHI + r * XROW;
        #pragma unroll
        for (int it = 0; it < 8; ++it) {
            int f4 = q + it * 4;
            float4 v = c4[r * 32 + f4];
            csum += v.x * v.x + v.y * v.y + v.z * v.z + v.w * v.w;
            uint2 hw, lw;
            split2(v.x, v.y, hw.x, lw.x);
            split2(v.z, v.w, hw.y, lw.y);
            *(uint2*)(rowp_h + f4 * 8) = hw;
            *(uint2*)(rowp_h + (SM_CLO - SM_CHI) + f4 * 8) = lw;
        }
        csum += __shfl_xor_sync(0xffffffffu, csum, 1);
        csum += __shfl_xor_sync(0xffffffffu, csum, 2);
        if (q == 0) c2s[r] = csum;
    }

    // ---- prologue: load tile 'start' into buffer 0 ----
    {
        const float4* xg = (const float4*)x + (size_t)(start * TILEP + r2) * 32;
        char* rowp = sm + SM_X0HI + r2 * XROW;
        float xsum = 0.f;
        #pragma unroll
        for (int i8 = 0; i8 < 16; ++i8) {
            int f4 = q2 + i8 * 2;
            float4 v = xg[f4];
            xsum += v.x * v.x + v.y * v.y + v.z * v.z + v.w * v.w;
            uint2 hw, lw;
            split2(v.x, v.y, hw.x, lw.x);
            split2(v.z, v.w, hw.y, lw.y);
            *(uint2*)(rowp + f4 * 8) = hw;
            *(uint2*)(rowp + XBUF + f4 * 8) = lw;
        }
        xsum += __shfl_xor_sync(0xffffffffu, xsum, 1);
        if (q2 == 0) x2s[r2] = xsum;
    }
    __syncthreads();

    // per-lane centroid norms for softmax (constant)
    float c2v[16];
    #pragma unroll
    for (int j = 0; j < 8; ++j) {
        c2v[2 * j]     = c2s[j * 8 + q4 * 2];
        c2v[2 * j + 1] = c2s[j * 8 + q4 * 2 + 1];
    }

    // persistent accumulators
    float acc2[8][4];
    #pragma unroll
    for (int j = 0; j < 8; ++j)
        #pragma unroll
        for (int c = 0; c < 4; ++c) acc2[j][c] = 0.f;
    float asum[16];
    #pragma unroll
    for (int i = 0; i < 16; ++i) asum[i] = 0.f;

    // ldmatrix base addresses (buffer-0 bases; add xoff for buffer 1)
    const uint32_t g1a  = smb + SM_X0HI + (uint32_t)((n0 + (lane & 15)) * XROW
                         + (((lane >> 4) & 1) << 4));
    const uint32_t g1b4 = smb + SM_CHI + (uint32_t)(((lane & 7) + (((lane >> 4) & 1) << 3)) * XROW
                         + (((lane >> 3) & 1) << 4));
    const uint32_t g2a  = smb + SM_X0HI + (uint32_t)(((((lane >> 4) & 1) << 3) + (lane & 7)) * XROW
                         + d0 * 2 + (((lane >> 3) & 1) << 4));
    const uint32_t g2b4 = smb + SM_AHI + (uint32_t)(((lane & 7) + (((lane >> 3) & 1) << 3)) * AROW
                         + (((lane >> 4) & 1) << 4));

    int p = 0;
    for (int it = 0; it < cnt; ++it) {
        const int t  = start + it;
        const int bt = t >> 5;
        const bool hasNext = (it + 1 < cnt);
        const uint32_t xoff = p ? (uint32_t)(SM_X1HI - SM_X0HI) : 0u;

        // ---- 1. prefetch next tile into registers ----
        float4 pf[16];
        if (hasNext) {
            const float4* xg = (const float4*)x + (size_t)((t + 1) * TILEP + r2) * 32;
            #pragma unroll
            for (int i8 = 0; i8 < 16; ++i8) pf[i8] = xg[q2 + i8 * 2];
        }

        // ---- 2. GEMM1 on buffer p ----
        float acc1[8][4];
        #pragma unroll
        for (int j = 0; j < 8; ++j)
            #pragma unroll
            for (int c = 0; c < 4; ++c) acc1[j][c] = 0.f;

        #pragma unroll
        for (int ks = 0; ks < 8; ++ks) {
            uint32_t ah[4], al[4];
            ldm_x4(g1a + xoff + ks * 32, ah);
            ldm_x4(g1a + xoff + XBUF + ks * 32, al);
            #pragma unroll
            for (int jj = 0; jj < 4; ++jj) {
                uint32_t bh[4], bl[4];
                uint32_t ba = g1b4 + jj * (16 * XROW) + ks * 32;
                ldm_x4(ba, bh);
                ldm_x4(ba + (SM_CLO - SM_CHI), bl);
                mma_bf16(acc1[2 * jj],     ah, bh);
                mma_bf16(acc1[2 * jj],     ah, bl);
                mma_bf16(acc1[2 * jj],     al, bh);
                mma_bf16(acc1[2 * jj + 1], ah, bh + 2);
                mma_bf16(acc1[2 * jj + 1], ah, bl + 2);
                mma_bf16(acc1[2 * jj + 1], al, bh + 2);
            }
        }

        // ---- 3. softmax in fragments (points pa = n0+r4, pb = pa+8) ----
        {
            const float* x2c = x2s + p * 128;
            const int pa = n0 + r4, pb = pa + 8;
            const float xa = x2c[pa], xb = x2c[pb];
            float lga[16], lgb[16];
            float ma = -1e30f, mb = -1e30f;
            #pragma unroll
            for (int j = 0; j < 8; ++j) {
                #pragma unroll
                for (int c = 0; c < 2; ++c) {
                    float da = fmaxf(xa + c2v[2 * j + c] - 2.f * acc1[j][c],     1e-30f);
                    float db = fmaxf(xb + c2v[2 * j + c] - 2.f * acc1[j][2 + c], 1e-30f);
                    float la = -ALPHA_ * (da * rsqrtf(da));
                    float lb = -ALPHA_ * (db * rsqrtf(db));
                    lga[2 * j + c] = la; lgb[2 * j + c] = lb;
                    ma = fmaxf(ma, la);  mb = fmaxf(mb, lb);
                }
            }
            ma = fmaxf(ma, __shfl_xor_sync(0xffffffffu, ma, 1));
            ma = fmaxf(ma, __shfl_xor_sync(0xffffffffu, ma, 2));
            mb = fmaxf(mb, __shfl_xor_sync(0xffffffffu, mb, 1));
            mb = fmaxf(mb, __shfl_xor_sync(0xffffffffu, mb, 2));
            float sa = 0.f, sb = 0.f;
            #pragma unroll
            for (int i = 0; i < 16; ++i) {
                lga[i] = __expf(lga[i] - ma); sa += lga[i];
                lgb[i] = __expf(lgb[i] - mb); sb += lgb[i];
            }
            sa += __shfl_xor_sync(0xffffffffu, sa, 1);
            sa += __shfl_xor_sync(0xffffffffu, sa, 2);
            sb += __shfl_xor_sync(0xffffffffu, sb, 1);
            sb += __shfl_xor_sync(0xffffffffu, sb, 2);
            const float inva = 1.0f / sa, invb = 1.0f / sb;
            char* aw_a = sm + SM_AHI + pa * AROW + q4 * 4;
            char* aw_b = sm + SM_AHI + pb * AROW + q4 * 4;
            #pragma unroll
            for (int j = 0; j < 8; ++j) {
                float a0 = lga[2 * j] * inva,  a1 = lga[2 * j + 1] * inva;
                float b0 = lgb[2 * j] * invb,  b1 = lgb[2 * j + 1] * invb;
                asum[2 * j]     += a0 + b0;
                asum[2 * j + 1] += a1 + b1;
                uint32_t hw, lw;
                split2(a0, a1, hw, lw);
                *(uint32_t*)(aw_a + j * 16) = hw;
                *(uint32_t*)(aw_a + (SM_ALO - SM_AHI) + j * 16) = lw;
                split2(b0, b1, hw, lw);
                *(uint32_t*)(aw_b + j * 16) = hw;
                *(uint32_t*)(aw_b + (SM_ALO - SM_AHI) + j * 16) = lw;
            }
        }

        // ---- 4. store prefetched tile into buffer p^1 ----
        if (hasNext) {
            char* rowp = sm + (p ? SM_X0HI : SM_X1HI) + r2 * XROW;
            float* x2n = x2s + (p ^ 1) * 128;
            float xsum = 0.f;
            #pragma unroll
            for (int i8 = 0; i8 < 16; ++i8) {
                int f4 = q2 + i8 * 2;
                float4 v = pf[i8];
                xsum += v.x * v.x + v.y * v.y + v.z * v.z + v.w * v.w;
                uint2 hw, lw;
                split2(v.x, v.y, hw.x, lw.x);
                split2(v.z, v.w, hw.y, lw.y);
                *(uint2*)(rowp + f4 * 8) = hw;
                *(uint2*)(rowp + XBUF + f4 * 8) = lw;
            }
            xsum += __shfl_xor_sync(0xffffffffu, xsum, 1);
            if (q2 == 0) x2n[r2] = xsum;
        }
        __syncthreads();   // 5: a-tiles + next x buffer visible

        // ---- 6. GEMM2 on buffer p ----
        #pragma unroll
        for (int ns = 0; ns < 8; ++ns) {
            uint32_t ah[4], al[4];
            ldm_x4t(g2a + xoff + ns * (16 * XROW), ah);
            ldm_x4t(g2a + xoff + XBUF + ns * (16 * XROW), al);
            #pragma unroll
            for (int jj = 0; jj < 4; ++jj) {
                uint32_t bh[4], bl[4];
                uint32_t ba = g2b4 + ns * (16 * AROW) + jj * 32;
                ldm_x4t(ba, bh);
                ldm_x4t(ba + (SM_ALO - SM_AHI), bl);
                mma_bf16(acc2[2 * jj],     ah, bh);
                mma_bf16(acc2[2 * jj],     ah, bl);
                mma_bf16(acc2[2 * jj],     al, bh);
                mma_bf16(acc2[2 * jj + 1], ah, bh + 2);
                mma_bf16(acc2[2 * jj + 1], ah, bl + 2);
                mma_bf16(acc2[2 * jj + 1], al, bh + 2);
            }
        }
        __syncthreads();   // 7: everyone done with buffer p and a-tiles

        // ---- flush on batch boundary / end, then maybe finalize ----
        const bool lastOfBatch = !hasNext || (((t + 1) >> 5) != bt);
        if (lastOfBatch) {
            float* gv = g_vlad + bt * K_ * D_;
            const int dd = d0 + r4;
            #pragma unroll
            for (int j = 0; j < 8; ++j) {
                const int kc = j * 8 + q4 * 2;
                atomicAdd(&gv[kc * D_ + dd],           acc2[j][0]);
                atomicAdd(&gv[(kc + 1) * D_ + dd],     acc2[j][1]);
                atomicAdd(&gv[kc * D_ + dd + 8],       acc2[j][2]);
                atomicAdd(&gv[(kc + 1) * D_ + dd + 8], acc2[j][3]);
                acc2[j][0] = acc2[j][1] = acc2[j][2] = acc2[j][3] = 0.f;
            }
            #pragma unroll
            for (int i = 0; i < 16; ++i) {
                float v = asum[i];
                v += __shfl_xor_sync(0xffffffffu, v, 4);
                v += __shfl_xor_sync(0xffffffffu, v, 8);
                v += __shfl_xor_sync(0xffffffffu, v, 16);
                if (lane < 4)
                    atomicAdd(&g_asum[bt * K_ + (i >> 1) * 8 + lane * 2 + (i & 1)], v);
                asum[i] = 0.f;
            }
            __threadfence();
            __syncthreads();
            if (tid == 0) {
                int nc = ctaOf(bt * 32 + 31) - ctaOf(bt * 32) + 1;
                s_isLast = (atomicAdd(&g_done[bt], 1) == nc - 1);
            }
            __syncthreads();
            if (s_isLast) {
                __threadfence();
                // finalize batch bt: vlad -= asum*c, L2-normalize, write out
                float vv[32], ssq = 0.f;
                #pragma unroll
                for (int m = 0; m < 32; ++m) {
                    const int e = m * 256 + tid;
                    const int k = e >> 7;
                    const int d = e & 127;
                    float val = fmaf(-g_asum[bt * K_ + k], cent[k * D_ + d],
                                     g_vlad[bt * K_ * D_ + e]);
                    vv[m] = val;
                    ssq = fmaf(val, val, ssq);
                }
                #pragma unroll
                for (int o = 16; o > 0; o >>= 1)
                    ssq += __shfl_xor_sync(0xffffffffu, ssq, o);
                if (lane == 0) s_red[w] = ssq;
                __syncthreads();
                if (tid == 0) {
                    float tot = 0.f;
                    #pragma unroll
                    for (int wv = 0; wv < 8; ++wv) tot += s_red[wv];
                    s_inv = 1.0f / fmaxf(sqrtf(tot), 1e-12f);
                }
                __syncthreads();
                const float inv = s_inv;
                #pragma unroll
                for (int m = 0; m < 32; ++m)
                    out[bt * K_ * D_ + m * 256 + tid] = vv[m] * inv;
            }
        }
        p ^= 1;
    }
}

extern "C" void kernel_launch(void* const* d_in, const int* in_sizes, int n_in,
                              void* d_out, int out_size) {
    const float* x    = (const float*)d_in[0];   // [32,4096,128] f32
    const float* cent = (const float*)d_in[1];   // [64,128] f32
    float* out = (float*)d_out;                  // [32,8192] f32
    (void)in_sizes; (void)n_in; (void)out_size;

    cudaFuncSetAttribute(vlad_main_mma, cudaFuncAttributeMaxDynamicSharedMemorySize,
                         SMEM_BYTES);

    vlad_zero<<<(B_ * K_ * D_ + 255) / 256, 256>>>();
    vlad_main_mma<<<NCTA_, 256, SMEM_BYTES>>>(x, cent, out);
}

// round 16
// speedup vs baseline: 2.8098x; 1.0457x over previous
#include <cuda_runtime.h>
#include <cstdint>

// VLAD pooling via warp-level bf16 MMA (mma.sync m16n8k16, base-target safe).
// x [32,4096,128] f32, centroids [64,128] f32 -> out [32, 8192] f32
//
// R16: 2 CTAs/SM. 64-point tiles (296 CTAs, 6-7 tiles each), no register
//      prefetch (inter-CTA overlap hides DRAM), single x buffer.
//      GEMM1 warp = (ng=w&3 -> 16 points) x (kh=w>>2 -> 32 clusters);
//      softmax = per-half max/expsum + exact cross-warp merge via smem.
//      GEMM2 warp = 16 dims x 64 clusters (as R14/15, 4 n-steps).

#define B_     32
#define N_     4096
#define D_     128
#define K_     64
#define ALPHA_ 100.0f
#define TILE_  64
#define NT_    2048          // 32 batches * 64 tiles
#define NCTA_  296
#define BASE_T 6
#define EXTRA_T 272          // NT_ - NCTA_*BASE_T (ctas 0..271 own 7 tiles)

#define XROW 272             // 128 bf16 = 256B, padded +16
#define AROW 144             // 64 bf16 = 128B, padded +16

#define SM_XHI 0             // [64][XROW]
#define SM_XLO 17408
#define SM_CHI 34816         // [64][XROW]
#define SM_CLO 52224
#define SM_AHI 69632         // [64][AROW]
#define SM_ALO 78848
#define SM_X2  88064         // 64 f32
#define SM_C2  88320         // 64 f32
#define SM_RED 88576         // float2 red[2][64] : (max, expsum) per k-half per point
#define SMEM_BYTES 89600

__device__ float g_vlad[B_ * K_ * D_];
__device__ float g_asum[B_ * K_];
__device__ int   g_done[B_];

__global__ void vlad_zero() {
    int i = blockIdx.x * blockDim.x + threadIdx.x;
    if (i < B_ * K_ * D_) g_vlad[i] = 0.f;
    if (i < B_ * K_) g_asum[i] = 0.f;
    if (i < B_) g_done[i] = 0;
}

// ---------------- helpers ---------------------------------------------------
__device__ __forceinline__ uint32_t smem_u32(const void* p) {
    uint32_t a;
    asm("{ .reg .u64 t; cvta.to.shared.u64 t, %1; cvt.u32.u64 %0, t; }" : "=r"(a) : "l"(p));
    return a;
}
__device__ __forceinline__ uint32_t pkbf(float lo, float hi) {
    uint32_t r;
    asm("cvt.rn.bf16x2.f32 %0, %1, %2;" : "=r"(r) : "f"(hi), "f"(lo));
    return r;
}
__device__ __forceinline__ void split2(float v0, float v1, uint32_t& hw, uint32_t& lw) {
    hw = pkbf(v0, v1);
    float h0 = __uint_as_float(hw << 16);
    float h1 = __uint_as_float(hw & 0xffff0000u);
    lw = pkbf(v0 - h0, v1 - h1);
}
__device__ __forceinline__ void ldm_x4(uint32_t addr, uint32_t* r) {
    asm volatile("ldmatrix.sync.aligned.m8n8.x4.shared.b16 {%0,%1,%2,%3}, [%4];"
        : "=r"(r[0]), "=r"(r[1]), "=r"(r[2]), "=r"(r[3]) : "r"(addr));
}
__device__ __forceinline__ void ldm_x4t(uint32_t addr, uint32_t* r) {
    asm volatile("ldmatrix.sync.aligned.m8n8.x4.trans.shared.b16 {%0,%1,%2,%3}, [%4];"
        : "=r"(r[0]), "=r"(r[1]), "=r"(r[2]), "=r"(r[3]) : "r"(addr));
}
__device__ __forceinline__ void mma_bf16(float* c, const uint32_t* a, const uint32_t* b) {
    asm volatile("mma.sync.aligned.m16n8k16.row.col.f32.bf16.bf16.f32 "
        "{%0,%1,%2,%3}, {%4,%5,%6,%7}, {%8,%9}, {%0,%1,%2,%3};"
        : "+f"(c[0]), "+f"(c[1]), "+f"(c[2]), "+f"(c[3])
        : "r"(a[0]), "r"(a[1]), "r"(a[2]), "r"(a[3]), "r"(b[0]), "r"(b[1]));
}
__device__ __forceinline__ int ctaOf(int t) {
    return t < 7 * EXTRA_T ? t / 7 : (t - EXTRA_T) / 6;
}

// ---------------------------------------------------------------------------
__global__ __launch_bounds__(256, 2)
void vlad_main_mma(const float* __restrict__ x, const float* __restrict__ cent,
                   float* __restrict__ out) {
    extern __shared__ char sm[];
    const uint32_t smb = smem_u32(sm);
    float*  x2s  = (float*)(sm + SM_X2);
    float*  c2s  = (float*)(sm + SM_C2);
    float2* red2 = (float2*)(sm + SM_RED);   // [kh][point]
    __shared__ int   s_isLast;
    __shared__ float s_red[8];
    __shared__ float s_inv;

    const int tid  = threadIdx.x;
    const int w    = tid >> 5;
    const int lane = tid & 31;
    const int cta  = blockIdx.x;
    const int r4   = lane >> 2;
    const int q4   = lane & 3;
    const int ng   = w & 3;          // GEMM1 n-group (16 points)
    const int kh   = w >> 2;         // GEMM1 k-half (32 clusters)
    const int n0   = ng * 16;
    const int d0   = w * 16;         // GEMM2 dim group
    const int q3   = tid & 3;        // x loader: 4 threads per row
    const int r3   = tid >> 2;       // row 0..63

    const int start = cta * BASE_T + (cta < EXTRA_T ? cta : EXTRA_T);
    const int cnt   = BASE_T + (cta < EXTRA_T ? 1 : 0);

    // ---- centroids -> CHI/CLO + c2 ----
    {
        const float4* c4 = (const float4*)cent;
        float csum = 0.f;
        char* rowp_h = sm + SM_CHI + r3 * XROW;
        #pragma unroll
        for (int it = 0; it < 8; ++it) {
            int f4 = q3 + it * 4;
            float4 v = c4[r3 * 32 + f4];
            csum += v.x * v.x + v.y * v.y + v.z * v.z + v.w * v.w;
            uint2 hw, lw;
            split2(v.x, v.y, hw.x, lw.x);
            split2(v.z, v.w, hw.y, lw.y);
            *(uint2*)(rowp_h + f4 * 8) = hw;
            *(uint2*)(rowp_h + (SM_CLO - SM_CHI) + f4 * 8) = lw;
        }
        csum += __shfl_xor_sync(0xffffffffu, csum, 1);
        csum += __shfl_xor_sync(0xffffffffu, csum, 2);
        if (q3 == 0) c2s[r3] = csum;
    }
    __syncthreads();

    // per-lane centroid norms for this warp's softmax slice
    float c2v[8];
    #pragma unroll
    for (int j = 0; j < 4; ++j) {
        c2v[2 * j]     = c2s[kh * 32 + j * 8 + q4 * 2];
        c2v[2 * j + 1] = c2s[kh * 32 + j * 8 + q4 * 2 + 1];
    }

    // persistent accumulators
    float acc2[8][4];
    #pragma unroll
    for (int j = 0; j < 8; ++j)
        #pragma unroll
        for (int c = 0; c < 4; ++c) acc2[j][c] = 0.f;
    float asum[8];
    #pragma unroll
    for (int i = 0; i < 8; ++i) asum[i] = 0.f;

    // ldmatrix base addresses
    const uint32_t g1a  = smb + SM_XHI + (uint32_t)((n0 + (lane & 15)) * XROW
                         + (((lane >> 4) & 1) << 4));
    const uint32_t g1b4 = smb + SM_CHI + (uint32_t)((kh * 32 + (lane & 7)
                         + (((lane >> 4) & 1) << 3)) * XROW
                         + (((lane >> 3) & 1) << 4));
    const uint32_t g2a  = smb + SM_XHI + (uint32_t)(((((lane >> 4) & 1) << 3) + (lane & 7)) * XROW
                         + d0 * 2 + (((lane >> 3) & 1) << 4));
    const uint32_t g2b4 = smb + SM_AHI + (uint32_t)(((lane & 7) + (((lane >> 3) & 1) << 3)) * AROW
                         + (((lane >> 4) & 1) << 4));

    for (int it = 0; it < cnt; ++it) {
        const int t  = start + it;
        const int bt = t >> 6;

        __syncthreads();   // previous tile's GEMM2 done with x / a-tiles

        // ---- load x tile -> XHI/XLO + x2 ----
        {
            const float4* xg = (const float4*)x + (size_t)(t * TILE_ + r3) * 32;
            char* rowp = sm + SM_XHI + r3 * XROW;
            float xsum = 0.f;
            #pragma unroll
            for (int i8 = 0; i8 < 8; ++i8) {
                int f4 = q3 + i8 * 4;
                float4 v = xg[f4];
                xsum += v.x * v.x + v.y * v.y + v.z * v.z + v.w * v.w;
                uint2 hw, lw;
                split2(v.x, v.y, hw.x, lw.x);
                split2(v.z, v.w, hw.y, lw.y);
                *(uint2*)(rowp + f4 * 8) = hw;
                *(uint2*)(rowp + (SM_XLO - SM_XHI) + f4 * 8) = lw;
            }
            xsum += __shfl_xor_sync(0xffffffffu, xsum, 1);
            xsum += __shfl_xor_sync(0xffffffffu, xsum, 2);
            if (q3 == 0) x2s[r3] = xsum;
        }
        __syncthreads();

        // ---- GEMM1: D1[16 n x 32 kc] = x.c^T, bf16 split ----
        float acc1[4][4];
        #pragma unroll
        for (int j = 0; j < 4; ++j)
            #pragma unroll
            for (int c = 0; c < 4; ++c) acc1[j][c] = 0.f;

        #pragma unroll
        for (int ks = 0; ks < 8; ++ks) {
            uint32_t ah[4], al[4];
            ldm_x4(g1a + ks * 32, ah);
            ldm_x4(g1a + (SM_XLO - SM_XHI) + ks * 32, al);
            #pragma unroll
            for (int jj = 0; jj < 2; ++jj) {
                uint32_t bh[4], bl[4];
                uint32_t ba = g1b4 + jj * (16 * XROW) + ks * 32;
                ldm_x4(ba, bh);
                ldm_x4(ba + (SM_CLO - SM_CHI), bl);
                mma_bf16(acc1[2 * jj],     ah, bh);
                mma_bf16(acc1[2 * jj],     ah, bl);
                mma_bf16(acc1[2 * jj],     al, bh);
                mma_bf16(acc1[2 * jj + 1], ah, bh + 2);
                mma_bf16(acc1[2 * jj + 1], ah, bl + 2);
                mma_bf16(acc1[2 * jj + 1], al, bh + 2);
            }
        }

        // ---- softmax part 1: per-half logits, max, expsum ----
        const int pa = n0 + r4, pb = pa + 8;
        float lga[8], lgb[8];
        {
            const float xa = x2s[pa], xb = x2s[pb];
            float ma = -1e30f, mb = -1e30f;
            #pragma unroll
            for (int j = 0; j < 4; ++j) {
                #pragma unroll
                for (int c = 0; c < 2; ++c) {
                    float da = fmaxf(xa + c2v[2 * j + c] - 2.f * acc1[j][c],     1e-30f);
                    float db = fmaxf(xb + c2v[2 * j + c] - 2.f * acc1[j][2 + c], 1e-30f);
                    float la = -ALPHA_ * (da * rsqrtf(da));
                    float lb = -ALPHA_ * (db * rsqrtf(db));
                    lga[2 * j + c] = la; lgb[2 * j + c] = lb;
                    ma = fmaxf(ma, la);  mb = fmaxf(mb, lb);
                }
            }
            ma = fmaxf(ma, __shfl_xor_sync(0xffffffffu, ma, 1));
            ma = fmaxf(ma, __shfl_xor_sync(0xffffffffu, ma, 2));
            mb = fmaxf(mb, __shfl_xor_sync(0xffffffffu, mb, 1));
            mb = fmaxf(mb, __shfl_xor_sync(0xffffffffu, mb, 2));
            float sa = 0.f, sb = 0.f;
            #pragma unroll
            for (int i = 0; i < 8; ++i) {
                lga[i] = __expf(lga[i] - ma); sa += lga[i];
                lgb[i] = __expf(lgb[i] - mb); sb += lgb[i];
            }
            sa += __shfl_xor_sync(0xffffffffu, sa, 1);
            sa += __shfl_xor_sync(0xffffffffu, sa, 2);
            sb += __shfl_xor_sync(0xffffffffu, sb, 1);
            sb += __shfl_xor_sync(0xffffffffu, sb, 2);
            if (q4 == 0) {
                red2[kh * 64 + pa] = make_float2(ma, sa);
                red2[kh * 64 + pb] = make_float2(mb, sb);
            }
        }
        __syncthreads();

        // ---- softmax part 2: exact merge of the two halves, write a ----
        {
            float2 a0 = red2[pa], a1 = red2[64 + pa];
            float2 b0 = red2[pb], b1 = red2[64 + pb];
            float mA = fmaxf(a0.x, a1.x);
            float sA = a0.y * __expf(a0.x - mA) + a1.y * __expf(a1.x - mA);
            float scA = __expf((kh ? a1.x : a0.x) - mA) / sA;
            float mB = fmaxf(b0.x, b1.x);
            float sB = b0.y * __expf(b0.x - mB) + b1.y * __expf(b1.x - mB);
            float scB = __expf((kh ? b1.x : b0.x) - mB) / sB;

            char* aw_a = sm + SM_AHI + pa * AROW + kh * 64 + q4 * 4;
            char* aw_b = sm + SM_AHI + pb * AROW + kh * 64 + q4 * 4;
            #pragma unroll
            for (int j = 0; j < 4; ++j) {
                float va0 = lga[2 * j] * scA, va1 = lga[2 * j + 1] * scA;
                float vb0 = lgb[2 * j] * scB, vb1 = lgb[2 * j + 1] * scB;
                asum[2 * j]     += va0 + vb0;
                asum[2 * j + 1] += va1 + vb1;
                uint32_t hw, lw;
                split2(va0, va1, hw, lw);
                *(uint32_t*)(aw_a + j * 16) = hw;
                *(uint32_t*)(aw_a + (SM_ALO - SM_AHI) + j * 16) = lw;
                split2(vb0, vb1, hw, lw);
                *(uint32_t*)(aw_b + j * 16) = hw;
                *(uint32_t*)(aw_b + (SM_ALO - SM_AHI) + j * 16) = lw;
            }
        }
        __syncthreads();   // a-tiles visible to all warps

        // ---- GEMM2: D2[16 d x 64 kc] += xT.a, trans loads, bf16 split ----
        #pragma unroll
        for (int ns = 0; ns < 4; ++ns) {
            uint32_t ah[4], al[4];
            ldm_x4t(g2a + ns * (16 * XROW), ah);
            ldm_x4t(g2a + (SM_XLO - SM_XHI) + ns * (16 * XROW), al);
            #pragma unroll
            for (int jj = 0; jj < 4; ++jj) {
                uint32_t bh[4], bl[4];
                uint32_t ba = g2b4 + ns * (16 * AROW) + jj * 32;
                ldm_x4t(ba, bh);
                ldm_x4t(ba + (SM_ALO - SM_AHI), bl);
                mma_bf16(acc2[2 * jj],     ah, bh);
                mma_bf16(acc2[2 * jj],     ah, bl);
                mma_bf16(acc2[2 * jj],     al, bh);
                mma_bf16(acc2[2 * jj + 1], ah, bh + 2);
                mma_bf16(acc2[2 * jj + 1], ah, bl + 2);
                mma_bf16(acc2[2 * jj + 1], al, bh + 2);
            }
        }

        // ---- flush on batch boundary / end, then maybe finalize ----
        const bool lastOfBatch = (it == cnt - 1) || (((t + 1) >> 6) != bt);
        if (lastOfBatch) {
            float* gv = g_vlad + bt * K_ * D_;
            const int dd = d0 + r4;
            #pragma unroll
            for (int j = 0; j < 8; ++j) {
                const int kc = j * 8 + q4 * 2;
                atomicAdd(&gv[kc * D_ + dd],           acc2[j][0]);
                atomicAdd(&gv[(kc + 1) * D_ + dd],     acc2[j][1]);
                atomicAdd(&gv[kc * D_ + dd + 8],       acc2[j][2]);
                atomicAdd(&gv[(kc + 1) * D_ + dd + 8], acc2[j][3]);
                acc2[j][0] = acc2[j][1] = acc2[j][2] = acc2[j][3] = 0.f;
            }
            #pragma unroll
            for (int i = 0; i < 8; ++i) {
                float v = asum[i];
                v += __shfl_xor_sync(0xffffffffu, v, 4);
                v += __shfl_xor_sync(0xffffffffu, v, 8);
                v += __shfl_xor_sync(0xffffffffu, v, 16);
                if (lane < 4)
                    atomicAdd(&g_asum[bt * K_ + kh * 32 + (i >> 1) * 8 + lane * 2 + (i & 1)], v);
                asum[i] = 0.f;
            }
            __threadfence();
            __syncthreads();
            if (tid == 0) {
                int nc = ctaOf(bt * 64 + 63) - ctaOf(bt * 64) + 1;
                s_isLast = (atomicAdd(&g_done[bt], 1) == nc - 1);
            }
            __syncthreads();
            if (s_isLast) {
                __threadfence();
                float vv[32], ssq = 0.f;
                #pragma unroll
                for (int m = 0; m < 32; ++m) {
                    const int e = m * 256 + tid;
                    const int k = e >> 7;
                    const int d = e & 127;
                    float val = fmaf(-g_asum[bt * K_ + k], cent[k * D_ + d],
                                     g_vlad[bt * K_ * D_ + e]);
                    vv[m] = val;
                    ssq = fmaf(val, val, ssq);
                }
                #pragma unroll
                for (int o = 16; o > 0; o >>= 1)
                    ssq += __shfl_xor_sync(0xffffffffu, ssq, o);
                if (lane == 0) s_red[w] = ssq;
                __syncthreads();
                if (tid == 0) {
                    float tot = 0.f;
                    #pragma unroll
                    for (int wv = 0; wv < 8; ++wv) tot += s_red[wv];
                    s_inv = 1.0f / fmaxf(sqrtf(tot), 1e-12f);
                }
                __syncthreads();
                const float inv = s_inv;
                #pragma unroll
                for (int m = 0; m < 32; ++m)
                    out[bt * K_ * D_ + m * 256 + tid] = vv[m] * inv;
            }
        }
    }
}

extern "C" void kernel_launch(void* const* d_in, const int* in_sizes, int n_in,
                              void* d_out, int out_size) {
    const float* x    = (const float*)d_in[0];   // [32,4096,128] f32
    const float* cent = (const float*)d_in[1];   // [64,128] f32
    float* out = (float*)d_out;                  // [32,8192] f32
    (void)in_sizes; (void)n_in; (void)out_size;

    cudaFuncSetAttribute(vlad_main_mma, cudaFuncAttributeMaxDynamicSharedMemorySize,
                         SMEM_BYTES);

    vlad_zero<<<(B_ * K_ * D_ + 255) / 256, 256>>>();
    vlad_main_mma<<<NCTA_, 256, SMEM_BYTES>>>(x, cent, out);
}